// round 2
// baseline (speedup 1.0000x reference)
#include <cuda_runtime.h>
#include <cstdint>

#define NN 50000
#define NE 800000
#define DD 128

// Scratch (allocation-free rule: __device__ globals)
__device__ float g_agg1[NN * DD];
__device__ float g_x1[NN * DD];
__device__ float g_agg2[NN * DD];
__device__ int g_is64;

__device__ __forceinline__ unsigned long long pack2(float x) {
    unsigned long long r;
    asm("mov.b64 %0, {%1, %1};" : "=l"(r) : "f"(x));
    return r;
}
__device__ __forceinline__ float2 unpack2(unsigned long long v) {
    float2 r;
    asm("mov.b64 {%0, %1}, %2;" : "=f"(r.x), "=f"(r.y) : "l"(v));
    return r;
}
__device__ __forceinline__ void fma2(unsigned long long& acc, unsigned long long a, unsigned long long b) {
    asm("fma.rn.f32x2 %0, %1, %2, %0;" : "+l"(acc) : "l"(a), "l"(b));
}

// Detect whether edge_index is int64 (odd 32-bit words all zero) or int32.
__global__ void detect_kernel(const int* __restrict__ ei_words) {
    if (threadIdx.x == 0) {
        int is64 = 1;
        for (int i = 0; i < 1024; i++) {
            if (ei_words[2 * i + 1] != 0) { is64 = 0; break; }
        }
        g_is64 = is64;
    }
}

// agg = (1+eps) * x
__global__ void init_agg_kernel(const float* __restrict__ x,
                                const float* __restrict__ eps,
                                float* __restrict__ agg) {
    int i = blockIdx.x * blockDim.x + threadIdx.x;
    float s = 1.0f + __ldg(eps);
    if (i < NN * DD / 4) {
        float4 v = __ldg((const float4*)x + i);
        v.x *= s; v.y *= s; v.z *= s; v.w *= s;
        ((float4*)agg)[i] = v;
    }
}

// One warp per edge: gather x[src] row (512B), vector-red into agg[dst]
__global__ void scatter_kernel(const float* __restrict__ x,
                               const void* __restrict__ ei_raw,
                               float* __restrict__ agg) {
    int e = blockIdx.x * (blockDim.x >> 5) + (threadIdx.x >> 5);
    if (e >= NE) return;
    int lane = threadIdx.x & 31;
    int src, dst;
    if (g_is64) {
        const long long* ei = (const long long*)ei_raw;
        src = (int)__ldg(ei + e);
        dst = (int)__ldg(ei + NE + e);
    } else {
        const int* ei = (const int*)ei_raw;
        src = __ldg(ei + e);
        dst = __ldg(ei + NE + e);
    }
    float4 v = __ldg((const float4*)(x + (size_t)src * DD) + lane);
    float* p = agg + (size_t)dst * DD + lane * 4;
    asm volatile("red.global.add.v4.f32 [%0], {%1,%2,%3,%4};"
                 :: "l"(p), "f"(v.x), "f"(v.y), "f"(v.z), "f"(v.w) : "memory");
}

// 64-row tile x 128-col GEMM from SMEM operands; W transposed with stride 132.
__device__ __forceinline__ void do_gemm(const float* __restrict__ sA,
                                        const float* __restrict__ sW,
                                        int r0, int c0,
                                        unsigned long long acc[4][4]) {
#pragma unroll
    for (int i = 0; i < 4; i++)
#pragma unroll
        for (int j = 0; j < 4; j++) acc[i][j] = 0ull;
#pragma unroll 8
    for (int k = 0; k < 128; k++) {
        ulonglong2 bv0 = *(const ulonglong2*)(sW + k * 132 + c0);
        ulonglong2 bv1 = *(const ulonglong2*)(sW + k * 132 + c0 + 4);
#pragma unroll
        for (int i = 0; i < 4; i++) {
            unsigned long long a = pack2(sA[(r0 + i) * 128 + k]);
            fma2(acc[i][0], a, bv0.x);
            fma2(acc[i][1], a, bv0.y);
            fma2(acc[i][2], a, bv1.x);
            fma2(acc[i][3], a, bv1.y);
        }
    }
}

// Fused: out = [relu?]( relu(H @ wA.T + bA) @ wB.T + bB ); optionally aggn = (1+epsn)*out
template <bool RELU_OUT, bool WRITE_AGG>
__global__ void __launch_bounds__(256, 1)
mlp_kernel(const float* __restrict__ H,
           const float* __restrict__ wA, const float* __restrict__ bA,
           const float* __restrict__ wB, const float* __restrict__ bB,
           float* __restrict__ out,
           float* __restrict__ aggn, const float* __restrict__ epsn) {
    extern __shared__ float sm[];
    float* sW1 = sm;                 // [128][132] transposed: sW1[k*132+c] = wA[c][k]
    float* sW2 = sW1 + 128 * 132;
    float* sH  = sW2 + 128 * 132;    // [64][128]
    float* sT  = sH + 64 * 128;      // [64][128]
    const int tid = threadIdx.x;

    float s2 = 0.0f;
    if (WRITE_AGG) s2 = 1.0f + __ldg(epsn);

    for (int i = tid; i < 128 * 128; i += 256) {
        int c = i >> 7, k = i & 127;
        sW1[k * 132 + c] = wA[i];
        sW2[k * 132 + c] = wB[i];
    }

    const int tx = tid & 15, ty = tid >> 4;
    const int r0 = ty * 4, c0 = tx * 8;
    const int NT = (NN + 63) / 64;  // 782 tiles

    for (int tile = blockIdx.x; tile < NT; tile += gridDim.x) {
        int rowBase = tile * 64;
        for (int i = tid; i < 64 * 32; i += 256) {
            int r = i >> 5, q = i & 31;
            int gr = rowBase + r;
            float4 v = make_float4(0.f, 0.f, 0.f, 0.f);
            if (gr < NN) v = __ldg((const float4*)H + (size_t)gr * 32 + q);
            ((float4*)sH)[i] = v;
        }
        __syncthreads();

        unsigned long long acc[4][4];
        do_gemm(sH, sW1, r0, c0, acc);
#pragma unroll
        for (int i = 0; i < 4; i++) {
#pragma unroll
            for (int j = 0; j < 4; j++) {
                float2 v = unpack2(acc[i][j]);
                int c = c0 + j * 2;
                float2 bb = *(const float2*)(bA + c);
                v.x = fmaxf(v.x + bb.x, 0.0f);
                v.y = fmaxf(v.y + bb.y, 0.0f);
                *(float2*)(sT + (r0 + i) * 128 + c) = v;
            }
        }
        __syncthreads();

        do_gemm(sT, sW2, r0, c0, acc);
#pragma unroll
        for (int i = 0; i < 4; i++) {
            int gr = rowBase + r0 + i;
            if (gr < NN) {
#pragma unroll
                for (int j = 0; j < 4; j++) {
                    float2 v = unpack2(acc[i][j]);
                    int c = c0 + j * 2;
                    float2 bb = *(const float2*)(bB + c);
                    v.x += bb.x; v.y += bb.y;
                    if (RELU_OUT) { v.x = fmaxf(v.x, 0.0f); v.y = fmaxf(v.y, 0.0f); }
                    *(float2*)(out + (size_t)gr * 128 + c) = v;
                    if (WRITE_AGG) {
                        float2 w = make_float2(v.x * s2, v.y * s2);
                        *(float2*)(aggn + (size_t)gr * 128 + c) = w;
                    }
                }
            }
        }
        __syncthreads();
    }
}

static const int SMEM_BYTES = (2 * 128 * 132 + 2 * 64 * 128) * 4;  // 200704 B

extern "C" void kernel_launch(void* const* d_in, const int* in_sizes, int n_in,
                              void* d_out, int out_size) {
    const float* features = (const float*)d_in[0];
    const void*  ei       = d_in[1];
    const float* w1a      = (const float*)d_in[2];
    const float* b1a      = (const float*)d_in[3];
    const float* w1b      = (const float*)d_in[4];
    const float* b1b      = (const float*)d_in[5];
    const float* eps1     = (const float*)d_in[6];
    const float* w2a      = (const float*)d_in[7];
    const float* b2a      = (const float*)d_in[8];
    const float* w2b      = (const float*)d_in[9];
    const float* b2b      = (const float*)d_in[10];
    const float* eps2     = (const float*)d_in[11];
    float* out = (float*)d_out;

    float *agg1, *x1, *agg2;
    cudaGetSymbolAddress((void**)&agg1, g_agg1);
    cudaGetSymbolAddress((void**)&x1, g_x1);
    cudaGetSymbolAddress((void**)&agg2, g_agg2);

    cudaFuncSetAttribute(mlp_kernel<true, true>,
                         cudaFuncAttributeMaxDynamicSharedMemorySize, SMEM_BYTES);
    cudaFuncSetAttribute(mlp_kernel<false, false>,
                         cudaFuncAttributeMaxDynamicSharedMemorySize, SMEM_BYTES);

    detect_kernel<<<1, 32>>>((const int*)ei);

    // Layer 1: agg1 = (1+eps1)*x + scatter(x); x1 = relu(MLP1(agg1)); agg2 = (1+eps2)*x1
    init_agg_kernel<<<(NN * DD / 4 + 255) / 256, 256>>>(features, eps1, agg1);
    scatter_kernel<<<NE / 8, 256>>>(features, ei, agg1);
    mlp_kernel<true, true><<<148, 256, SMEM_BYTES>>>(agg1, w1a, b1a, w1b, b1b, x1, agg2, eps2);

    // Layer 2: agg2 += scatter(x1); out = MLP2(agg2)
    scatter_kernel<<<NE / 8, 256>>>(x1, ei, agg2);
    mlp_kernel<false, false><<<148, 256, SMEM_BYTES>>>(agg2, w2a, b2a, w2b, b2b, out, nullptr, nullptr);
}

// round 4
// speedup vs baseline: 1.2679x; 1.2679x over previous
#include <cuda_runtime.h>
#include <cstdint>

#define NN 50000
#define NE 800000

// Scratch (allocation-free rule: __device__ globals)
__device__ float g_agg1[NN * 128];
__device__ float g_x1[NN * 128];
__device__ float g_agg2[NN * 128];
__device__ int g_is64;

__device__ __forceinline__ unsigned long long pack2(float x) {
    unsigned long long r;
    asm("mov.b64 %0, {%1, %1};" : "=l"(r) : "f"(x));
    return r;
}
__device__ __forceinline__ float2 unpack2(unsigned long long v) {
    float2 r;
    asm("mov.b64 {%0, %1}, %2;" : "=f"(r.x), "=f"(r.y) : "l"(v));
    return r;
}
__device__ __forceinline__ void fma2(unsigned long long& acc, unsigned long long a, unsigned long long b) {
    asm("fma.rn.f32x2 %0, %1, %2, %0;" : "+l"(acc) : "l"(a), "l"(b));
}

// Detect whether edge_index is int64 (odd 32-bit words all zero) or int32.
__global__ void detect_kernel(const int* __restrict__ w) {
    __shared__ int any;
    if (threadIdx.x == 0) any = 0;
    __syncthreads();
    int nz = 0;
    for (int k = threadIdx.x; k < 1024; k += 256) nz |= __ldg(w + 2 * k + 1);
    if (nz) any = 1;
    __syncthreads();
    if (threadIdx.x == 0) g_is64 = any ? 0 : 1;
}

// agg = (1+eps) * x
__global__ void init_agg_kernel(const float* __restrict__ x,
                                const float* __restrict__ eps,
                                float* __restrict__ agg) {
    int i = blockIdx.x * blockDim.x + threadIdx.x;
    float s = 1.0f + __ldg(eps);
    if (i < NN * 128 / 4) {
        float4 v = __ldg((const float4*)x + i);
        v.x *= s; v.y *= s; v.z *= s; v.w *= s;
        ((float4*)agg)[i] = v;
    }
}

// One warp per edge: gather x[src] row (512B), vector-red into agg[dst]
__global__ void scatter_kernel(const float* __restrict__ x,
                               const void* __restrict__ ei_raw,
                               float* __restrict__ agg) {
    int e = blockIdx.x * (blockDim.x >> 5) + (threadIdx.x >> 5);
    if (e >= NE) return;
    int lane = threadIdx.x & 31;
    int src, dst;
    if (g_is64) {
        const long long* ei = (const long long*)ei_raw;
        src = (int)__ldg(ei + e);
        dst = (int)__ldg(ei + NE + e);
    } else {
        const int* ei = (const int*)ei_raw;
        src = __ldg(ei + e);
        dst = __ldg(ei + NE + e);
    }
    float4 v = __ldg((const float4*)(x + (size_t)src * 128) + lane);
    float* p = agg + (size_t)dst * 128 + lane * 4;
    asm volatile("red.global.add.v4.f32 [%0], {%1,%2,%3,%4};"
                 :: "l"(p), "f"(v.x), "f"(v.y), "f"(v.z), "f"(v.w) : "memory");
}

// ===================== fused MLP: 128x128 tile, 8x8/thread, FFMA2 =====================
// SMEM float offsets
#define F_W1  0                       // [128][132] transposed: sW[k*132+c] = w[c*128+k]
#define F_W2  (128 * 132)
#define F_AT  (2 * 128 * 132)         // [128][128] A tile, reused as T tile
#define F_BA  (F_AT + 128 * 128)
#define F_BB  (F_BA + 128)
#define SMEM_FLOATS (F_BB + 128)
#define SMEM_BYTES (SMEM_FLOATS * 4)  // 201728 B

// acc[i][j] covers rows r0+i (i<8), col pair c0+2j (j<4  -> 8 cols)
__device__ __forceinline__ void do_gemm(const float* __restrict__ sA,
                                        const float* __restrict__ sW,
                                        int r0, int c0,
                                        unsigned long long acc[8][4]) {
#pragma unroll
    for (int i = 0; i < 8; i++)
#pragma unroll
        for (int j = 0; j < 4; j++) acc[i][j] = 0ull;

#pragma unroll 2
    for (int k4 = 0; k4 < 128; k4 += 4) {
        float4 a[8];
#pragma unroll
        for (int i = 0; i < 8; i++)
            a[i] = *(const float4*)(sA + (r0 + i) * 128 + k4);
        const float* af = (const float*)a;
#pragma unroll
        for (int kk = 0; kk < 4; kk++) {
            ulonglong2 b0 = *(const ulonglong2*)(sW + (k4 + kk) * 132 + c0);
            ulonglong2 b1 = *(const ulonglong2*)(sW + (k4 + kk) * 132 + c0 + 4);
#pragma unroll
            for (int i = 0; i < 8; i++) {
                unsigned long long av = pack2(af[i * 4 + kk]);
                fma2(acc[i][0], av, b0.x);
                fma2(acc[i][1], av, b0.y);
                fma2(acc[i][2], av, b1.x);
                fma2(acc[i][3], av, b1.y);
            }
        }
    }
}

template <bool RELU_OUT, bool WRITE_AGG>
__global__ void __launch_bounds__(256, 1)
mlp_kernel(const float* __restrict__ H,
           const float* __restrict__ wA, const float* __restrict__ bA,
           const float* __restrict__ wB, const float* __restrict__ bB,
           float* __restrict__ out,
           float* __restrict__ aggn, const float* __restrict__ epsn) {
    extern __shared__ float sm[];
    float* sW1 = sm + F_W1;
    float* sW2 = sm + F_W2;
    float* sAT = sm + F_AT;
    float* ba  = sm + F_BA;
    float* bb  = sm + F_BB;
    const int tid = threadIdx.x;

    float s2 = 0.0f;
    if (WRITE_AGG) s2 = 1.0f + __ldg(epsn);

    for (int i = tid; i < 128 * 128; i += 256) {
        int c = i >> 7, k = i & 127;
        sW1[k * 132 + c] = __ldg(wA + i);
        sW2[k * 132 + c] = __ldg(wB + i);
    }
    if (tid < 128) {
        ba[tid] = __ldg(bA + tid);
        bb[tid] = __ldg(bB + tid);
    }

    const int tx = tid & 15, ty = tid >> 4;
    const int r0 = ty * 8, c0 = tx * 8;
    const int NT = (NN + 127) / 128;  // 391 tiles

    for (int tile = blockIdx.x; tile < NT; tile += gridDim.x) {
        int rowBase = tile << 7;
        // ---- fill A tile ----
        for (int i = tid; i < 128 * 32; i += 256) {
            int r = i >> 5, q = i & 31;
            int gr = rowBase + r;
            float4 v = make_float4(0.f, 0.f, 0.f, 0.f);
            if (gr < NN) v = __ldg((const float4*)H + (size_t)gr * 32 + q);
            ((float4*)sAT)[i] = v;
        }
        __syncthreads();

        unsigned long long acc[8][4];
        do_gemm(sAT, sW1, r0, c0, acc);
        __syncthreads();  // everyone done reading A before T overwrites it

        // epilogue1: bias + relu -> sAT (as T)
#pragma unroll
        for (int i = 0; i < 8; i++) {
            float2 v0 = unpack2(acc[i][0]);
            float2 v1 = unpack2(acc[i][1]);
            float2 v2 = unpack2(acc[i][2]);
            float2 v3 = unpack2(acc[i][3]);
            v0.x = fmaxf(v0.x + ba[c0 + 0], 0.f); v0.y = fmaxf(v0.y + ba[c0 + 1], 0.f);
            v1.x = fmaxf(v1.x + ba[c0 + 2], 0.f); v1.y = fmaxf(v1.y + ba[c0 + 3], 0.f);
            v2.x = fmaxf(v2.x + ba[c0 + 4], 0.f); v2.y = fmaxf(v2.y + ba[c0 + 5], 0.f);
            v3.x = fmaxf(v3.x + ba[c0 + 6], 0.f); v3.y = fmaxf(v3.y + ba[c0 + 7], 0.f);
            *(float4*)(sAT + (r0 + i) * 128 + c0)     = make_float4(v0.x, v0.y, v1.x, v1.y);
            *(float4*)(sAT + (r0 + i) * 128 + c0 + 4) = make_float4(v2.x, v2.y, v3.x, v3.y);
        }
        __syncthreads();

        do_gemm(sAT, sW2, r0, c0, acc);

        // epilogue2: bias [+relu] -> global
#pragma unroll
        for (int i = 0; i < 8; i++) {
            int gr = rowBase + r0 + i;
            if (gr < NN) {
                float2 v0 = unpack2(acc[i][0]);
                float2 v1 = unpack2(acc[i][1]);
                float2 v2 = unpack2(acc[i][2]);
                float2 v3 = unpack2(acc[i][3]);
                v0.x += bb[c0 + 0]; v0.y += bb[c0 + 1];
                v1.x += bb[c0 + 2]; v1.y += bb[c0 + 3];
                v2.x += bb[c0 + 4]; v2.y += bb[c0 + 5];
                v3.x += bb[c0 + 6]; v3.y += bb[c0 + 7];
                if (RELU_OUT) {
                    v0.x = fmaxf(v0.x, 0.f); v0.y = fmaxf(v0.y, 0.f);
                    v1.x = fmaxf(v1.x, 0.f); v1.y = fmaxf(v1.y, 0.f);
                    v2.x = fmaxf(v2.x, 0.f); v2.y = fmaxf(v2.y, 0.f);
                    v3.x = fmaxf(v3.x, 0.f); v3.y = fmaxf(v3.y, 0.f);
                }
                float* po = out + (size_t)gr * 128 + c0;
                *(float4*)(po)     = make_float4(v0.x, v0.y, v1.x, v1.y);
                *(float4*)(po + 4) = make_float4(v2.x, v2.y, v3.x, v3.y);
                if (WRITE_AGG) {
                    float* pa = aggn + (size_t)gr * 128 + c0;
                    *(float4*)(pa)     = make_float4(s2 * v0.x, s2 * v0.y, s2 * v1.x, s2 * v1.y);
                    *(float4*)(pa + 4) = make_float4(s2 * v2.x, s2 * v2.y, s2 * v3.x, s2 * v3.y);
                }
            }
        }
        __syncthreads();  // before next tile's A fill
    }
}

extern "C" void kernel_launch(void* const* d_in, const int* in_sizes, int n_in,
                              void* d_out, int out_size) {
    const float* features = (const float*)d_in[0];
    const void*  ei       = d_in[1];
    const float* w1a      = (const float*)d_in[2];
    const float* b1a      = (const float*)d_in[3];
    const float* w1b      = (const float*)d_in[4];
    const float* b1b      = (const float*)d_in[5];
    const float* eps1     = (const float*)d_in[6];
    const float* w2a      = (const float*)d_in[7];
    const float* b2a      = (const float*)d_in[8];
    const float* w2b      = (const float*)d_in[9];
    const float* b2b      = (const float*)d_in[10];
    const float* eps2     = (const float*)d_in[11];
    float* out = (float*)d_out;

    float *agg1, *x1, *agg2;
    cudaGetSymbolAddress((void**)&agg1, g_agg1);
    cudaGetSymbolAddress((void**)&x1, g_x1);
    cudaGetSymbolAddress((void**)&agg2, g_agg2);

    cudaFuncSetAttribute(mlp_kernel<true, true>,
                         cudaFuncAttributeMaxDynamicSharedMemorySize, SMEM_BYTES);
    cudaFuncSetAttribute(mlp_kernel<false, false>,
                         cudaFuncAttributeMaxDynamicSharedMemorySize, SMEM_BYTES);

    detect_kernel<<<1, 256>>>((const int*)ei);

    // Layer 1: agg1 = (1+eps1)*x + scatter(x); x1 = relu(MLP1(agg1)); agg2 = (1+eps2)*x1
    init_agg_kernel<<<(NN * 128 / 4 + 255) / 256, 256>>>(features, eps1, agg1);
    scatter_kernel<<<NE / 8, 256>>>(features, ei, agg1);
    mlp_kernel<true, true><<<148, 256, SMEM_BYTES>>>(agg1, w1a, b1a, w1b, b1b, x1, agg2, eps2);

    // Layer 2: agg2 += scatter(x1); out = MLP2(agg2)
    scatter_kernel<<<NE / 8, 256>>>(x1, ei, agg2);
    mlp_kernel<false, false><<<148, 256, SMEM_BYTES>>>(agg2, w2a, b2a, w2b, b2b, out, nullptr, nullptr);
}

// round 5
// speedup vs baseline: 1.4258x; 1.1245x over previous
#include <cuda_runtime.h>
#include <cstdint>

#define NN 50000
#define NE 800000

// Scratch (allocation-free rule: __device__ globals)
__device__ float g_agg1[NN * 128];
__device__ float g_x1[NN * 128];
__device__ float g_agg2[NN * 128];
__device__ int g_is64;
__device__ int g_deg[NN];
__device__ int g_rowptr[NN + 1];
__device__ int g_cur[NN];
__device__ int g_esrc[NE];

__device__ __forceinline__ unsigned long long pack2(float x) {
    unsigned long long r;
    asm("mov.b64 %0, {%1, %1};" : "=l"(r) : "f"(x));
    return r;
}
__device__ __forceinline__ float2 unpack2(unsigned long long v) {
    float2 r;
    asm("mov.b64 {%0, %1}, %2;" : "=f"(r.x), "=f"(r.y) : "l"(v));
    return r;
}
__device__ __forceinline__ void fma2(unsigned long long& acc, unsigned long long a, unsigned long long b) {
    asm("fma.rn.f32x2 %0, %1, %2, %0;" : "+l"(acc) : "l"(a), "l"(b));
}

// ======================= CSR build =======================
__global__ void detect_and_zero_kernel(const int* __restrict__ w) {
    // grid-stride zero of deg; block 0 also detects dtype
    int i = blockIdx.x * blockDim.x + threadIdx.x;
    for (int k = i; k < NN; k += gridDim.x * blockDim.x) g_deg[k] = 0;
    if (blockIdx.x == 0) {
        __shared__ int any;
        if (threadIdx.x == 0) any = 0;
        __syncthreads();
        int nz = 0;
        for (int k = threadIdx.x; k < 1024; k += blockDim.x) nz |= __ldg(w + 2 * k + 1);
        if (nz) any = 1;
        __syncthreads();
        if (threadIdx.x == 0) g_is64 = any ? 0 : 1;
    }
}

__device__ __forceinline__ void load_edge(const void* ei_raw, int e, int& src, int& dst) {
    if (g_is64) {
        const long long* ei = (const long long*)ei_raw;
        src = (int)__ldg(ei + e);
        dst = (int)__ldg(ei + NE + e);
    } else {
        const int* ei = (const int*)ei_raw;
        src = __ldg(ei + e);
        dst = __ldg(ei + NE + e);
    }
}

__global__ void hist_kernel(const void* __restrict__ ei_raw) {
    int e = blockIdx.x * blockDim.x + threadIdx.x;
    if (e < NE) {
        int src, dst;
        load_edge(ei_raw, e, src, dst);
        atomicAdd(&g_deg[dst], 1);
    }
}

// single-block exclusive scan: rowptr/cur from deg
__global__ void scan_kernel() {
    __shared__ int part[1024];
    const int tid = threadIdx.x;
    const int CH = (NN + 1023) / 1024;  // 49
    int base = tid * CH;
    int s = 0;
#pragma unroll 4
    for (int i = 0; i < CH; i++) {
        int idx = base + i;
        if (idx < NN) s += g_deg[idx];
    }
    part[tid] = s;
    __syncthreads();
    for (int off = 1; off < 1024; off <<= 1) {
        int t = (tid >= off) ? part[tid - off] : 0;
        __syncthreads();
        part[tid] += t;
        __syncthreads();
    }
    int run = part[tid] - s;  // exclusive prefix
    for (int i = 0; i < CH; i++) {
        int idx = base + i;
        if (idx < NN) {
            g_rowptr[idx] = run;
            g_cur[idx] = run;
            run += g_deg[idx];
        }
    }
    if (tid == 0) g_rowptr[NN] = NE;
}

__global__ void fill_kernel(const void* __restrict__ ei_raw) {
    int e = blockIdx.x * blockDim.x + threadIdx.x;
    if (e < NE) {
        int src, dst;
        load_edge(ei_raw, e, src, dst);
        int p = atomicAdd(&g_cur[dst], 1);
        g_esrc[p] = src;
    }
}

// ======================= CSR aggregation =======================
// One warp per node: agg[i] = (1+eps)*x[i] + sum_{j in N(i)} x[j]
__global__ void agg_kernel(const float* __restrict__ x,
                           const float* __restrict__ eps,
                           float* __restrict__ agg) {
    int node = blockIdx.x * (blockDim.x >> 5) + (threadIdx.x >> 5);
    if (node >= NN) return;
    int lane = threadIdx.x & 31;
    float s = 1.0f + __ldg(eps);
    int beg = __ldg(g_rowptr + node), end = __ldg(g_rowptr + node + 1);

    float4 a = __ldg((const float4*)(x + (size_t)node * 128) + lane);
    float4 acc = make_float4(s * a.x, s * a.y, s * a.z, s * a.w);

    int j = beg;
    for (; j + 4 <= end; j += 4) {
        int s0 = __ldg(g_esrc + j), s1 = __ldg(g_esrc + j + 1);
        int s2 = __ldg(g_esrc + j + 2), s3 = __ldg(g_esrc + j + 3);
        float4 v0 = __ldg((const float4*)(x + (size_t)s0 * 128) + lane);
        float4 v1 = __ldg((const float4*)(x + (size_t)s1 * 128) + lane);
        float4 v2 = __ldg((const float4*)(x + (size_t)s2 * 128) + lane);
        float4 v3 = __ldg((const float4*)(x + (size_t)s3 * 128) + lane);
        acc.x += v0.x + v1.x; acc.y += v0.y + v1.y;
        acc.z += v0.z + v1.z; acc.w += v0.w + v1.w;
        acc.x += v2.x + v3.x; acc.y += v2.y + v3.y;
        acc.z += v2.z + v3.z; acc.w += v2.w + v3.w;
    }
    for (; j < end; j++) {
        int s0 = __ldg(g_esrc + j);
        float4 v = __ldg((const float4*)(x + (size_t)s0 * 128) + lane);
        acc.x += v.x; acc.y += v.y; acc.z += v.z; acc.w += v.w;
    }
    ((float4*)(agg + (size_t)node * 128))[lane] = acc;
}

// ===================== fused MLP: 128x128 tile, 8x8/thread, FFMA2 =====================
#define F_W1  0                       // [128][132] transposed: sW[k*132+c] = w[c*128+k]
#define F_W2  (128 * 132)
#define F_AT  (2 * 128 * 132)         // [128][128] A tile, reused as T tile
#define F_BA  (F_AT + 128 * 128)
#define F_BB  (F_BA + 128)
#define SMEM_FLOATS (F_BB + 128)
#define SMEM_BYTES (SMEM_FLOATS * 4)  // 201728 B

__device__ __forceinline__ void do_gemm(const float* __restrict__ sA,
                                        const float* __restrict__ sW,
                                        int r0, int c0,
                                        unsigned long long acc[8][4]) {
#pragma unroll
    for (int i = 0; i < 8; i++)
#pragma unroll
        for (int j = 0; j < 4; j++) acc[i][j] = 0ull;

#pragma unroll 2
    for (int k4 = 0; k4 < 128; k4 += 4) {
        float4 a[8];
#pragma unroll
        for (int i = 0; i < 8; i++)
            a[i] = *(const float4*)(sA + (r0 + i) * 128 + k4);
        const float* af = (const float*)a;
#pragma unroll
        for (int kk = 0; kk < 4; kk++) {
            ulonglong2 b0 = *(const ulonglong2*)(sW + (k4 + kk) * 132 + c0);
            ulonglong2 b1 = *(const ulonglong2*)(sW + (k4 + kk) * 132 + c0 + 4);
#pragma unroll
            for (int i = 0; i < 8; i++) {
                unsigned long long av = pack2(af[i * 4 + kk]);
                fma2(acc[i][0], av, b0.x);
                fma2(acc[i][1], av, b0.y);
                fma2(acc[i][2], av, b1.x);
                fma2(acc[i][3], av, b1.y);
            }
        }
    }
}

template <bool RELU_OUT>
__global__ void __launch_bounds__(256, 1)
mlp_kernel(const float* __restrict__ H,
           const float* __restrict__ wA, const float* __restrict__ bA,
           const float* __restrict__ wB, const float* __restrict__ bB,
           float* __restrict__ out) {
    extern __shared__ float sm[];
    float* sW1 = sm + F_W1;
    float* sW2 = sm + F_W2;
    float* sAT = sm + F_AT;
    float* ba  = sm + F_BA;
    float* bb  = sm + F_BB;
    const int tid = threadIdx.x;

    for (int i = tid; i < 128 * 128; i += 256) {
        int c = i >> 7, k = i & 127;
        sW1[k * 132 + c] = __ldg(wA + i);
        sW2[k * 132 + c] = __ldg(wB + i);
    }
    if (tid < 128) {
        ba[tid] = __ldg(bA + tid);
        bb[tid] = __ldg(bB + tid);
    }

    const int tx = tid & 15, ty = tid >> 4;
    const int r0 = ty * 8, c0 = tx * 8;
    const int NT = (NN + 127) / 128;  // 391 tiles

    for (int tile = blockIdx.x; tile < NT; tile += gridDim.x) {
        int rowBase = tile << 7;
        for (int i = tid; i < 128 * 32; i += 256) {
            int r = i >> 5, q = i & 31;
            int gr = rowBase + r;
            float4 v = make_float4(0.f, 0.f, 0.f, 0.f);
            if (gr < NN) v = __ldg((const float4*)H + (size_t)gr * 32 + q);
            ((float4*)sAT)[i] = v;
        }
        __syncthreads();

        unsigned long long acc[8][4];
        do_gemm(sAT, sW1, r0, c0, acc);
        __syncthreads();

#pragma unroll
        for (int i = 0; i < 8; i++) {
            float2 v0 = unpack2(acc[i][0]);
            float2 v1 = unpack2(acc[i][1]);
            float2 v2 = unpack2(acc[i][2]);
            float2 v3 = unpack2(acc[i][3]);
            v0.x = fmaxf(v0.x + ba[c0 + 0], 0.f); v0.y = fmaxf(v0.y + ba[c0 + 1], 0.f);
            v1.x = fmaxf(v1.x + ba[c0 + 2], 0.f); v1.y = fmaxf(v1.y + ba[c0 + 3], 0.f);
            v2.x = fmaxf(v2.x + ba[c0 + 4], 0.f); v2.y = fmaxf(v2.y + ba[c0 + 5], 0.f);
            v3.x = fmaxf(v3.x + ba[c0 + 6], 0.f); v3.y = fmaxf(v3.y + ba[c0 + 7], 0.f);
            *(float4*)(sAT + (r0 + i) * 128 + c0)     = make_float4(v0.x, v0.y, v1.x, v1.y);
            *(float4*)(sAT + (r0 + i) * 128 + c0 + 4) = make_float4(v2.x, v2.y, v3.x, v3.y);
        }
        __syncthreads();

        do_gemm(sAT, sW2, r0, c0, acc);

#pragma unroll
        for (int i = 0; i < 8; i++) {
            int gr = rowBase + r0 + i;
            if (gr < NN) {
                float2 v0 = unpack2(acc[i][0]);
                float2 v1 = unpack2(acc[i][1]);
                float2 v2 = unpack2(acc[i][2]);
                float2 v3 = unpack2(acc[i][3]);
                v0.x += bb[c0 + 0]; v0.y += bb[c0 + 1];
                v1.x += bb[c0 + 2]; v1.y += bb[c0 + 3];
                v2.x += bb[c0 + 4]; v2.y += bb[c0 + 5];
                v3.x += bb[c0 + 6]; v3.y += bb[c0 + 7];
                if (RELU_OUT) {
                    v0.x = fmaxf(v0.x, 0.f); v0.y = fmaxf(v0.y, 0.f);
                    v1.x = fmaxf(v1.x, 0.f); v1.y = fmaxf(v1.y, 0.f);
                    v2.x = fmaxf(v2.x, 0.f); v2.y = fmaxf(v2.y, 0.f);
                    v3.x = fmaxf(v3.x, 0.f); v3.y = fmaxf(v3.y, 0.f);
                }
                float* po = out + (size_t)gr * 128 + c0;
                *(float4*)(po)     = make_float4(v0.x, v0.y, v1.x, v1.y);
                *(float4*)(po + 4) = make_float4(v2.x, v2.y, v3.x, v3.y);
            }
        }
        __syncthreads();
    }
}

extern "C" void kernel_launch(void* const* d_in, const int* in_sizes, int n_in,
                              void* d_out, int out_size) {
    const float* features = (const float*)d_in[0];
    const void*  ei       = d_in[1];
    const float* w1a      = (const float*)d_in[2];
    const float* b1a      = (const float*)d_in[3];
    const float* w1b      = (const float*)d_in[4];
    const float* b1b      = (const float*)d_in[5];
    const float* eps1     = (const float*)d_in[6];
    const float* w2a      = (const float*)d_in[7];
    const float* b2a      = (const float*)d_in[8];
    const float* w2b      = (const float*)d_in[9];
    const float* b2b      = (const float*)d_in[10];
    const float* eps2     = (const float*)d_in[11];
    float* out = (float*)d_out;

    float *agg1, *x1, *agg2;
    cudaGetSymbolAddress((void**)&agg1, g_agg1);
    cudaGetSymbolAddress((void**)&x1, g_x1);
    cudaGetSymbolAddress((void**)&agg2, g_agg2);

    cudaFuncSetAttribute(mlp_kernel<true>,
                         cudaFuncAttributeMaxDynamicSharedMemorySize, SMEM_BYTES);
    cudaFuncSetAttribute(mlp_kernel<false>,
                         cudaFuncAttributeMaxDynamicSharedMemorySize, SMEM_BYTES);

    // CSR build (once per call, reused by both layers)
    detect_and_zero_kernel<<<64, 256>>>((const int*)ei);
    hist_kernel<<<(NE + 255) / 256, 256>>>(ei);
    scan_kernel<<<1, 1024>>>();
    fill_kernel<<<(NE + 255) / 256, 256>>>(ei);

    // Layer 1
    agg_kernel<<<(NN * 32 + 255) / 256, 256>>>(features, eps1, agg1);
    mlp_kernel<true><<<148, 256, SMEM_BYTES>>>(agg1, w1a, b1a, w1b, b1b, x1);

    // Layer 2
    agg_kernel<<<(NN * 32 + 255) / 256, 256>>>(x1, eps2, agg2);
    mlp_kernel<false><<<148, 256, SMEM_BYTES>>>(agg2, w2a, b2a, w2b, b2b, out);
}